// round 17
// baseline (speedup 1.0000x reference)
#include <cuda_runtime.h>
#include <math.h>

#define HIDDEN   256
#define MAXLEN   256
#define NLAYERS  4
#define VOCAB    50257
#define LOGIT_BLOCKS ((VOCAB + 31) / 32)   // 1571 blocks, 32 rows each

// ---------------- scratch (device globals; stateless across replays) --------
__device__ float g_attnlog[MAXLEN];
__device__ float g_cin[2 * HIDDEN];     // [embedded | attn_applied]
__device__ float g_x[HIDDEN];
__device__ float g_xf[HIDDEN];
__device__ float g_gi[NLAYERS * 3 * HIDDEN];
__device__ float g_gh[NLAYERS * 3 * HIDDEN];
__device__ float g_esum[2048];          // per-logit-block exp sums

__device__ __forceinline__ float warp_sum(float s) {
#pragma unroll
    for (int o = 16; o; o >>= 1) s += __shfl_down_sync(0xffffffffu, s, o);
    return s;
}
__device__ __forceinline__ float dot4(float4 a, float4 b) {
    return a.x * b.x + a.y * b.y + a.z * b.z + a.w * b.w;
}
#define CLUSTER_SYNC() do { \
    asm volatile("barrier.cluster.arrive.aligned;" ::: "memory"); \
    asm volatile("barrier.cluster.wait.aligned;"   ::: "memory"); \
} while (0)

// ================= serial chain: ONE 8-CTA cluster, 7 cluster.syncs =========
__global__ __launch_bounds__(256, 1) __cluster_dims__(8, 1, 1)
void k_chain(const int* __restrict__ token,  const float* __restrict__ hidden,
             const float* __restrict__ enc,  const float* __restrict__ emb,
             const float* __restrict__ attn_w, const float* __restrict__ attn_b,
             const float* __restrict__ comb_w, const float* __restrict__ comb_b,
             const float* __restrict__ wih,  const float* __restrict__ whh,
             const float* __restrict__ bih,  const float* __restrict__ bhh,
             float* __restrict__ out_attnw,  float* __restrict__ out_hidden)
{
    __shared__ float sh[2 * HIDDEN];
    const int r = blockIdx.x, tid = threadIdx.x;
    const int w = tid >> 5, lane = tid & 31;
    const int tok = token[0];

    // ---- P0: attn logits; CTA r owns rows r*32 .. r*32+31 (4 rows/warp) ----
#pragma unroll
    for (int j = 0; j < 4; j++) {
        int row = r * 32 + w * 4 + j;
        const float4* W = (const float4*)(attn_w + (size_t)row * 2 * HIDDEN);
        float s = 0.f;
#pragma unroll
        for (int c = 0; c < 4; c++) {
            float4 a = __ldg(&W[lane + 32 * c]);
            int base = (lane + 32 * c) * 4;            // 0..511
            float4 v = (base < HIDDEN)
                ? __ldg((const float4*)&emb[(size_t)tok * HIDDEN + base])
                : __ldg((const float4*)&hidden[base - HIDDEN]);
            s += dot4(a, v);
        }
        s = warp_sum(s);
        if (lane == 0) __stcg(&g_attnlog[row], s + __ldg(&attn_b[row]));
    }
    if (r == 0) __stcg(&g_cin[tid], __ldg(&emb[(size_t)tok * HIDDEN + tid]));
    __threadfence();
    CLUSTER_SYNC();

    // ---- P1: redundant softmax + applied for t = r*32 + w*4 + j ----
    {
        float v = __ldcg(&g_attnlog[tid]);
        sh[tid] = v; __syncthreads();
        for (int s2 = 128; s2; s2 >>= 1) {
            if (tid < s2) sh[tid] = fmaxf(sh[tid], sh[tid + s2]);
            __syncthreads();
        }
        float m = sh[0]; __syncthreads();
        float e = expf(v - m);
        sh[tid] = e; __syncthreads();
        for (int s2 = 128; s2; s2 >>= 1) {
            if (tid < s2) sh[tid] += sh[tid + s2];
            __syncthreads();
        }
        float wgt = e / sh[0]; __syncthreads();
        sh[HIDDEN + tid] = wgt;
        if (r == 0) out_attnw[tid] = wgt;
        __syncthreads();
    }
#pragma unroll
    for (int j = 0; j < 4; j++) {
        int t = r * 32 + w * 4 + j;
        float a = 0.f;
#pragma unroll
        for (int k = 0; k < 8; k++) {
            int l2 = lane + k * 32;
            a += sh[HIDDEN + l2] * __ldg(&enc[l2 * HIDDEN + t]);
        }
        a = warp_sum(a);
        if (lane == 0) __stcg(&g_cin[HIDDEN + t], a);
    }
    __threadfence();
    CLUSTER_SYNC();

    // ---- P2: comb + relu, rows r*32 + w*4 + j ----
    __syncthreads();
    sh[tid]          = __ldcg(&g_cin[tid]);
    sh[HIDDEN + tid] = __ldcg(&g_cin[HIDDEN + tid]);
    __syncthreads();
#pragma unroll
    for (int j = 0; j < 4; j++) {
        int row = r * 32 + w * 4 + j;
        const float4* W = (const float4*)(comb_w + (size_t)row * 2 * HIDDEN);
        const float4* V = (const float4*)sh;
        float s = 0.f;
#pragma unroll
        for (int c = 0; c < 4; c++)
            s += dot4(__ldg(&W[lane + 32 * c]), V[lane + 32 * c]);
        s = warp_sum(s);
        if (lane == 0) __stcg(&g_x[row], fmaxf(s + __ldg(&comb_b[row]), 0.f));
    }
    __threadfence();
    CLUSTER_SYNC();

    // ---- GRU: per layer, CTA r owns gi+gh rows r*96 .. r*96+95 (12/warp) ----
    __syncthreads();
    sh[tid] = __ldcg(&g_x[tid]);
    __syncthreads();

    for (int l = 0; l < NLAYERS; l++) {
        const float4* HV = (const float4*)(hidden + l * HIDDEN);
        float4 hv0 = __ldg(&HV[lane]),  hv1 = __ldg(&HV[lane + 32]);
        const float4* XV = (const float4*)sh;
        float4 xv0 = XV[lane],          xv1 = XV[lane + 32];
#pragma unroll 4
        for (int j = 0; j < 12; j++) {
            int row = r * 96 + w * 12 + j;             // 0..767
            const float4* Wi = (const float4*)(wih + ((size_t)l * 3 * HIDDEN + row) * HIDDEN);
            const float4* Wh = (const float4*)(whh + ((size_t)l * 3 * HIDDEN + row) * HIDDEN);
            float si = dot4(__ldg(&Wi[lane]), xv0) + dot4(__ldg(&Wi[lane + 32]), xv1);
            float sa = dot4(__ldg(&Wh[lane]), hv0) + dot4(__ldg(&Wh[lane + 32]), hv1);
            si = warp_sum(si);
            sa = warp_sum(sa);
            if (lane == 0) {
                __stcg(&g_gi[l * 3 * HIDDEN + row], si + __ldg(&bih[l * 3 * HIDDEN + row]));
                __stcg(&g_gh[l * 3 * HIDDEN + row], sa + __ldg(&bhh[l * 3 * HIDDEN + row]));
            }
        }
        __threadfence();
        CLUSTER_SYNC();

        // redundant elementwise combine (t = tid)
        const float* gi = g_gi + l * 3 * HIDDEN;
        const float* gh = g_gh + l * 3 * HIDDEN;
        float ir = __ldcg(&gi[tid]), iz = __ldcg(&gi[HIDDEN + tid]), in_ = __ldcg(&gi[2 * HIDDEN + tid]);
        float hr = __ldcg(&gh[tid]), hz = __ldcg(&gh[HIDDEN + tid]), hn  = __ldcg(&gh[2 * HIDDEN + tid]);
        float rg = 1.f / (1.f + expf(-(ir + hr)));
        float zg = 1.f / (1.f + expf(-(iz + hz)));
        float ng = tanhf(in_ + rg * hn);
        float hp = __ldg(&hidden[l * HIDDEN + tid]);
        float h  = (1.f - zg) * ng + zg * hp;
        if (r == 0) {
            out_hidden[l * HIDDEN + tid] = h;
            if (l == NLAYERS - 1) __stcg(&g_xf[tid], h);
        }
        __syncthreads();
        sh[tid] = h;
        __syncthreads();
    }
}

// ============= vocab logits: 4 rows/warp + per-block exp-sum ================
__global__ void __launch_bounds__(256) k_logits(
    const float* __restrict__ out_w, const float* __restrict__ out_b,
    float* __restrict__ logits)
{
    __shared__ float sx[HIDDEN];
    __shared__ float se[8];
    int tid = threadIdx.x, w = tid >> 5, lane = tid & 31;
    sx[tid] = __ldcg(&g_xf[tid]);
    __syncthreads();
    const float4* V = (const float4*)sx;
    float4 v0 = V[lane], v1 = V[lane + 32];
    int r0 = (blockIdx.x * 8 + w) * 4;
    float s0 = 0.f, s1 = 0.f, s2 = 0.f, s3 = 0.f;
    if (r0 + 0 < VOCAB) { const float4* W = (const float4*)(out_w + (size_t)(r0 + 0) * HIDDEN); s0 = dot4(__ldg(&W[lane]), v0) + dot4(__ldg(&W[lane + 32]), v1); }
    if (r0 + 1 < VOCAB) { const float4* W = (const float4*)(out_w + (size_t)(r0 + 1) * HIDDEN); s1 = dot4(__ldg(&W[lane]), v0) + dot4(__ldg(&W[lane + 32]), v1); }
    if (r0 + 2 < VOCAB) { const float4* W = (const float4*)(out_w + (size_t)(r0 + 2) * HIDDEN); s2 = dot4(__ldg(&W[lane]), v0) + dot4(__ldg(&W[lane + 32]), v1); }
    if (r0 + 3 < VOCAB) { const float4* W = (const float4*)(out_w + (size_t)(r0 + 3) * HIDDEN); s3 = dot4(__ldg(&W[lane]), v0) + dot4(__ldg(&W[lane + 32]), v1); }
#pragma unroll
    for (int o = 16; o; o >>= 1) {
        s0 += __shfl_down_sync(0xffffffffu, s0, o);
        s1 += __shfl_down_sync(0xffffffffu, s1, o);
        s2 += __shfl_down_sync(0xffffffffu, s2, o);
        s3 += __shfl_down_sync(0xffffffffu, s3, o);
    }
    if (lane == 0) {
        float e = 0.f;
        if (r0 + 0 < VOCAB) { s0 += __ldg(&out_b[r0 + 0]); logits[r0 + 0] = s0; e += expf(s0); }
        if (r0 + 1 < VOCAB) { s1 += __ldg(&out_b[r0 + 1]); logits[r0 + 1] = s1; e += expf(s1); }
        if (r0 + 2 < VOCAB) { s2 += __ldg(&out_b[r0 + 2]); logits[r0 + 2] = s2; e += expf(s2); }
        if (r0 + 3 < VOCAB) { s3 += __ldg(&out_b[r0 + 3]); logits[r0 + 3] = s3; e += expf(s3); }
        se[w] = e;
    }
    __syncthreads();
    if (tid == 0) {
        float t = se[0] + se[1] + se[2] + se[3] + se[4] + se[5] + se[6] + se[7];
        __stcg(&g_esum[blockIdx.x], t);
    }
}

// ===== tail: redundant stateless lse reduce (no cross-block sync) ===========
__global__ void __launch_bounds__(256) k_tail(float* __restrict__ logits)
{
    __shared__ float red[256];
    int tid = threadIdx.x, blk = blockIdx.x;
    float s = 0.f;
    for (int i = tid; i < LOGIT_BLOCKS; i += 256) s += __ldcg(&g_esum[i]);
    red[tid] = s; __syncthreads();
    for (int st = 128; st; st >>= 1) {
        if (tid < st) red[tid] += red[tid + st];
        __syncthreads();
    }
    float lse = logf(red[0]);
    for (int i = blk * 256 + tid; i < VOCAB; i += 64 * 256) logits[i] -= lse;
}

// ---------------------------------------------------------------------------
extern "C" void kernel_launch(void* const* d_in, const int* in_sizes, int n_in,
                              void* d_out, int out_size) {
    const int*   token  = (const int*)  d_in[0];
    const float* hidden = (const float*)d_in[1];
    const float* enc    = (const float*)d_in[2];
    const float* emb    = (const float*)d_in[3];
    const float* attn_w = (const float*)d_in[4];
    const float* attn_b = (const float*)d_in[5];
    const float* comb_w = (const float*)d_in[6];
    const float* comb_b = (const float*)d_in[7];
    const float* g_wih  = (const float*)d_in[8];
    const float* g_whh  = (const float*)d_in[9];
    const float* g_bih  = (const float*)d_in[10];
    const float* g_bhh  = (const float*)d_in[11];
    const float* out_w  = (const float*)d_in[12];
    const float* out_b  = (const float*)d_in[13];

    float* out        = (float*)d_out;
    float* out_logits = out;
    float* out_hidden = out + VOCAB;
    float* out_attnw  = out + VOCAB + NLAYERS * HIDDEN;

    k_chain<<<8, 256>>>(token, hidden, enc, emb, attn_w, attn_b, comb_w, comb_b,
                        g_wih, g_whh, g_bih, g_bhh, out_attnw, out_hidden);
    k_logits<<<LOGIT_BLOCKS, 256>>>(out_w, out_b, out_logits);
    k_tail<<<64, 256>>>(out_logits);
}